// round 1
// baseline (speedup 1.0000x reference)
#include <cuda_runtime.h>

#define T_LEN 100000
#define H 33
#define G 132          // 4*H gate rows
#define NUM_PRED 20

// Scratch for the precomputed input projection (+8 steps of prefetch padding).
// __device__ global array: allowed scratch (no runtime allocation).
__device__ float g_xproj[(T_LEN + 8) * G];

// ---------- packed f32x2 helpers (Blackwell FFMA2: 2x FMA per issue) ----------
__device__ __forceinline__ unsigned long long fma2(unsigned long long a,
                                                   unsigned long long b,
                                                   unsigned long long c) {
    unsigned long long d;
    asm("fma.rn.f32x2 %0, %1, %2, %3;" : "=l"(d) : "l"(a), "l"(b), "l"(c));
    return d;
}
__device__ __forceinline__ unsigned long long mul2(unsigned long long a,
                                                   unsigned long long b) {
    unsigned long long d;
    asm("mul.rn.f32x2 %0, %1, %2;" : "=l"(d) : "l"(a), "l"(b));
    return d;
}
__device__ __forceinline__ unsigned long long add2(unsigned long long a,
                                                   unsigned long long b) {
    unsigned long long d;
    asm("add.rn.f32x2 %0, %1, %2;" : "=l"(d) : "l"(a), "l"(b));
    return d;
}

// ---------- accurate-enough activations (MUFU.EX2 + MUFU.RCP, ~1e-6 err) ----------
// Both are saturating-safe: exp overflow -> inf -> rcp -> 0, no NaNs.
__device__ __forceinline__ float sigf(float x) {
    float e = __expf(-x);
    return __fdividef(1.0f, 1.0f + e);
}
__device__ __forceinline__ float tanhf_acc(float x) {
    float e = __expf(-2.0f * x);
    return fmaf(2.0f, __fdividef(1.0f, 1.0f + e), -1.0f);
}

// ============================================================================
// Kernel 1: x_proj[t, r] = b1[r] + sum_j W_ih1[r, j] * mvts[t, j]
// Fully parallel; ~66 MB of traffic -> tens of microseconds.
// ============================================================================
__global__ __launch_bounds__(G, 1) void xproj_kernel(
    const float* __restrict__ mvts, const float* __restrict__ W_ih1,
    const float* __restrict__ b_ih1, const float* __restrict__ b_hh1) {
    __shared__ float xrow[2][36];
    const int tid = threadIdx.x;                 // gate-row index 0..131
    const int BT  = 50;                          // timesteps per block
    const int t0  = blockIdx.x * BT;

    float w[H];
#pragma unroll
    for (int j = 0; j < H; j++) w[j] = W_ih1[tid * H + j];
    const float b = b_ih1[tid] + b_hh1[tid];

    if (tid < H) xrow[0][tid] = mvts[(size_t)t0 * H + tid];
    __syncthreads();

    for (int i = 0; i < BT; i++) {
        const int buf = i & 1;
        if (tid < H && (i + 1) < BT)
            xrow[buf ^ 1][tid] = mvts[(size_t)(t0 + i + 1) * H + tid];
        float acc = b;
#pragma unroll
        for (int j = 0; j < H; j++) acc = fmaf(w[j], xrow[buf][j], acc);
        g_xproj[(size_t)(t0 + i) * G + tid] = acc;
        __syncthreads();
    }
}

// ============================================================================
// Kernel 2: the sequential LSTM scan (1 block, 132 threads) + 20 decode steps.
// Thread r owns gate-row r: W row lives in registers as 16 packed f32x2 + 1.
// h lives in shared (33 floats); gates exchanged through shared with 2 barriers.
// xp prefetched 4..7 steps ahead (L2-resident since kernel 1 just wrote it).
// ============================================================================
__global__ __launch_bounds__(G, 1) void scan_kernel(
    const float* __restrict__ W_hh1,
    const float* __restrict__ W_ih2,
    const float* __restrict__ b_ih2,
    const float* __restrict__ b_hh2,
    float* __restrict__ out) {
    __shared__ __align__(16) float h_sh[36];
    __shared__ float gates_sh[G];
    const int tid = threadIdx.x;

    // Pack recurrent weight row into f32x2 registers
    unsigned long long ww[16];
    float w32;
    {
        const float* wr = W_hh1 + tid * H;
#pragma unroll
        for (int i = 0; i < 16; i++) {
            unsigned lo = __float_as_uint(wr[2 * i]);
            unsigned hi = __float_as_uint(wr[2 * i + 1]);
            ww[i] = ((unsigned long long)hi << 32) | (unsigned long long)lo;
        }
        w32 = wr[32];
    }

    if (tid < 36) h_sh[tid] = 0.0f;
    float c = 0.0f;
    __syncthreads();

    // r = addend + w32*h[32] + sum_{j<32} w[j]*h[j]   (packed, 4 ILP chains)
    auto matvec = [&](const unsigned long long* w, float w32v, float addend) -> float {
        const ulonglong2* hp = reinterpret_cast<const ulonglong2*>(h_sh);
        unsigned long long hh[16];
#pragma unroll
        for (int i = 0; i < 8; i++) {
            ulonglong2 v = hp[i];        // LDS.128
            hh[2 * i]     = v.x;
            hh[2 * i + 1] = v.y;
        }
        unsigned long long a0 = mul2(w[0], hh[0]);
        unsigned long long a1 = mul2(w[1], hh[1]);
        unsigned long long a2 = mul2(w[2], hh[2]);
        unsigned long long a3 = mul2(w[3], hh[3]);
#pragma unroll
        for (int i = 4; i < 16; i += 4) {
            a0 = fma2(w[i + 0], hh[i + 0], a0);
            a1 = fma2(w[i + 1], hh[i + 1], a1);
            a2 = fma2(w[i + 2], hh[i + 2], a2);
            a3 = fma2(w[i + 3], hh[i + 3], a3);
        }
        a0 = add2(a0, a1);
        a2 = add2(a2, a3);
        a0 = add2(a0, a2);
        float sx, sy;
        asm("mov.b64 {%0, %1}, %2;" : "=f"(sx), "=f"(sy) : "l"(a0));
        float r = sx + sy + addend;
        return fmaf(w32v, h_sh[32], r);
    };

#define LSTM_STEP(XP)                                                   \
    do {                                                                \
        float r = matvec(ww, w32, (XP));                                \
        gates_sh[tid] = r;                                              \
        __syncthreads();                                                \
        if (tid < H) {                                                  \
            float gi = gates_sh[tid];                                   \
            float gf = gates_sh[tid + H];                               \
            float gg = gates_sh[tid + 2 * H];                           \
            float go = gates_sh[tid + 3 * H];                           \
            c = sigf(gf) * c + sigf(gi) * tanhf_acc(gg);                \
            h_sh[tid] = sigf(go) * tanhf_acc(c);                        \
        }                                                               \
        __syncthreads();                                                \
    } while (0)

    float xp0 = g_xproj[0 * G + tid];
    float xp1 = g_xproj[1 * G + tid];
    float xp2 = g_xproj[2 * G + tid];
    float xp3 = g_xproj[3 * G + tid];

    for (int t = 0; t < T_LEN; t += 4) {
        // prefetch next group (valid padded reads past T_LEN; values unused)
        float xn0 = g_xproj[(t + 4) * G + tid];
        float xn1 = g_xproj[(t + 5) * G + tid];
        float xn2 = g_xproj[(t + 6) * G + tid];
        float xn3 = g_xproj[(t + 7) * G + tid];
        LSTM_STEP(xp0);
        LSTM_STEP(xp1);
        LSTM_STEP(xp2);
        LSTM_STEP(xp3);
        xp0 = xn0; xp1 = xn1; xp2 = xn2; xp3 = xn3;
    }
#undef LSTM_STEP

    // ---------------- autoregressive decode (20 steps, c resets to 0) ---------
    unsigned long long ww2[16];
    float w32b;
    {
        const float* wr = W_ih2 + tid * H;
#pragma unroll
        for (int i = 0; i < 16; i++) {
            unsigned lo = __float_as_uint(wr[2 * i]);
            unsigned hi = __float_as_uint(wr[2 * i + 1]);
            ww2[i] = ((unsigned long long)hi << 32) | (unsigned long long)lo;
        }
        w32b = wr[32];
    }
    const float b2 = b_ih2[tid] + b_hh2[tid];

    for (int s = 0; s < NUM_PRED; s++) {
        float r = matvec(ww2, w32b, b2);
        gates_sh[tid] = r;
        __syncthreads();
        if (tid < H) {
            float gi = gates_sh[tid];
            float gg = gates_sh[tid + 2 * H];
            float go = gates_sh[tid + 3 * H];
            float cc = sigf(gi) * tanhf_acc(gg);   // f-gate * c0 == 0
            float hv = sigf(go) * tanhf_acc(cc);
            out[s * H + tid] = hv;
            h_sh[tid] = hv;
        }
        __syncthreads();
    }
}

// ============================================================================
// Entry point. Input order per metadata: mvts, W_ih1, W_hh1, b_ih1, b_hh1,
// W_ih2, W_hh2, b_ih2, b_hh2. Output: (20, 33) float32. W_hh2 is unused
// (reference decode carries no recurrent state).
// ============================================================================
extern "C" void kernel_launch(void* const* d_in, const int* in_sizes, int n_in,
                              void* d_out, int out_size) {
    const float* mvts  = (const float*)d_in[0];
    const float* W_ih1 = (const float*)d_in[1];
    const float* W_hh1 = (const float*)d_in[2];
    const float* b_ih1 = (const float*)d_in[3];
    const float* b_hh1 = (const float*)d_in[4];
    const float* W_ih2 = (const float*)d_in[5];
    const float* b_ih2 = (const float*)d_in[7];
    const float* b_hh2 = (const float*)d_in[8];
    float* out = (float*)d_out;

    xproj_kernel<<<T_LEN / 50, G>>>(mvts, W_ih1, b_ih1, b_hh1);
    scan_kernel<<<1, G>>>(W_hh1, W_ih2, b_ih2, b_hh2, out);
}